// round 4
// baseline (speedup 1.0000x reference)
#include <cuda_runtime.h>
#include <math.h>

// ---------------- scratch (no allocation allowed) ----------------
#define MAXN   262144
#define SCAN_BLK 1024          // threads per scan block
#define TILE   4096            // segments per scan block (4 per thread)
#define MAX_NB 128
__device__ int    g_off[MAXN];     // exclusive prefix within scan tile
__device__ int    g_bsum[MAX_NB];  // exclusive tile offsets after k2
__device__ double g_acc[4];        // lp, la, lw, ls sums
__device__ int    g_done = 0;      // completion counter for folded finalize

// ---------------- kernel 1: tile-local exclusive scan (warp-scan, 2 barriers) --
__global__ void __launch_bounds__(SCAN_BLK) k_scan_local(const int* __restrict__ counts, int N) {
    __shared__ int wsum[32];
    const unsigned FULL = 0xffffffffu;
    int tid = threadIdx.x, lane = tid & 31, w = tid >> 5;
    int base4 = blockIdx.x * TILE + tid * 4;

    int4 v = make_int4(0, 0, 0, 0);
    if (base4 + 3 < N) v = *(const int4*)(counts + base4);
    else {
        if (base4 + 0 < N) v.x = counts[base4 + 0];
        if (base4 + 1 < N) v.y = counts[base4 + 1];
        if (base4 + 2 < N) v.z = counts[base4 + 2];
        if (base4 + 3 < N) v.w = counts[base4 + 3];
    }
    int s = v.x + v.y + v.z + v.w;

    // warp inclusive scan of per-thread sums
    int si = s;
    #pragma unroll
    for (int o = 1; o < 32; o <<= 1) {
        int t = __shfl_up_sync(FULL, si, o);
        if (lane >= o) si += t;
    }
    if (lane == 31) wsum[w] = si;
    __syncthreads();
    if (w == 0) {
        int ws = wsum[lane];
        int wi = ws;
        #pragma unroll
        for (int o = 1; o < 32; o <<= 1) {
            int t = __shfl_up_sync(FULL, wi, o);
            if (lane >= o) wi += t;
        }
        wsum[lane] = wi - ws;   // exclusive warp offset
        if (lane == 31 && wi > 0) g_bsum[blockIdx.x] = wi;  // tile total
        if (lane == 31) g_bsum[blockIdx.x] = wi;
    }
    __syncthreads();

    int base = wsum[w] + (si - s);   // exclusive prefix of this thread's 4
    if (base4 + 3 < N) {
        int4 o4;
        o4.x = base;
        o4.y = base + v.x;
        o4.z = base + v.x + v.y;
        o4.w = base + v.x + v.y + v.z;
        *(int4*)(g_off + base4) = o4;
    } else {
        int b = base;
        if (base4 + 0 < N) { g_off[base4 + 0] = b; b += v.x; }
        if (base4 + 1 < N) { g_off[base4 + 1] = b; b += v.y; }
        if (base4 + 2 < N) { g_off[base4 + 2] = b; b += v.z; }
        if (base4 + 3 < N) { g_off[base4 + 3] = b; }
    }
}

// ---------------- kernel 2: scan tile sums -> exclusive; zero accumulators ----
__global__ void k_scan_bsum(int NB) {
    __shared__ int sh[MAX_NB];
    int tid = threadIdx.x;
    int v = (tid < NB) ? g_bsum[tid] : 0;
    sh[tid] = v;
    __syncthreads();
    #pragma unroll
    for (int o = 1; o < MAX_NB; o <<= 1) {
        int t = (tid >= o) ? sh[tid - o] : 0;
        __syncthreads();
        sh[tid] += t;
        __syncthreads();
    }
    if (tid < NB) g_bsum[tid] = sh[tid] - v;   // exclusive
    if (tid < 4)  g_acc[tid] = 0.0;
}

// ---------------- kernel 3: main segmented loss + folded finalize -------------
__global__ void __launch_bounds__(256) k_main(
    const float* __restrict__ pred,
    const float* __restrict__ gt,
    const int*   __restrict__ counts,
    float* __restrict__ out,
    int N)
{
    const unsigned FULL = 0xffffffffu;
    const int lane   = threadIdx.x & 31;
    const int wInBlk = threadIdx.x >> 5;
    const int warpId = (blockIdx.x * blockDim.x + threadIdx.x) >> 5;
    const int nWarps = (gridDim.x * blockDim.x) >> 5;

    float a0 = 0.f, a1 = 0.f, a2 = 0.f, a3 = 0.f;

    for (int s = warpId; s < N; s += nWarps) {
        int cnt = __ldg(counts + s);            // uniform broadcast
        if (cnt > 0) {
            int off = g_off[s] + g_bsum[s / TILE];

            const float* pr = pred + (size_t)s * 6;
            float2 p01 = *(const float2*)(pr);
            float2 p23 = *(const float2*)(pr + 2);
            float2 p45 = *(const float2*)(pr + 4);

            bool valid = lane < cnt;
            int  row   = off + (valid ? lane : 0);
            const float* gr = gt + (size_t)row * 6;
            float2 g01 = *(const float2*)(gr);
            float2 g23 = *(const float2*)(gr + 2);   // upfront: same cache lines as xy
            float2 g45 = *(const float2*)(gr + 4);

            float dx = p01.x - g01.x, dy = p01.y - g01.y;
            float d  = valid ? (dx * dx + dy * dy) : __int_as_float(0x7f800000);

            // pack (dist_bits, lane): u64 min == lexicographic (dist, idx) min
            unsigned long long key =
                ((unsigned long long)__float_as_uint(d) << 6) | (unsigned)lane;
            #pragma unroll
            for (int o = 16; o; o >>= 1) {
                unsigned long long ok = __shfl_down_sync(FULL, key, o);
                key = (ok < key) ? ok : key;
            }
            key = __shfl_sync(FULL, key, 0);        // broadcast winner
            int   ml   = (int)(key & 63u);
            float dmin = __uint_as_float((unsigned)(key >> 6));

            // gather nearest row's fields from the winning lane (no reload)
            float n2 = __shfl_sync(FULL, g23.x, ml);
            float n3 = __shfl_sync(FULL, g23.y, ml);
            float n4 = __shfl_sync(FULL, g45.x, ml);
            float n5 = __shfl_sync(FULL, g45.y, ml);

            if (lane == 0) {
                a0 += 1.0f - expf(dmin * (-1.0f / 0.045f));   // 2*sigma^2 = 0.045
                a1 += fabsf(p23.x - n2) + fabsf(p23.y - n3);
                float dd = p45.x - n4, ad = fabsf(dd);
                a2 += (ad < 1.0f) ? 0.5f * dd * dd : ad - 0.5f;
                float x = p45.y, t = n5;
                if (t > 0.0f)
                    a3 += fmaxf(x, 0.0f) - x * t + log1pf(expf(-fabsf(x)));
            }
        }
    }

    // block reduce (lane 0 of each warp holds partials)
    __shared__ float sh[8][4];
    if (lane == 0) {
        sh[wInBlk][0] = a0; sh[wInBlk][1] = a1;
        sh[wInBlk][2] = a2; sh[wInBlk][3] = a3;
    }
    __syncthreads();
    if (threadIdx.x == 0) {
        float b0 = 0.f, b1 = 0.f, b2 = 0.f, b3 = 0.f;
        int nw = blockDim.x >> 5;
        for (int w = 0; w < nw; w++) {
            b0 += sh[w][0]; b1 += sh[w][1]; b2 += sh[w][2]; b3 += sh[w][3];
        }
        atomicAdd(&g_acc[0], (double)b0);
        atomicAdd(&g_acc[1], (double)b1);
        atomicAdd(&g_acc[2], (double)b2);
        atomicAdd(&g_acc[3], (double)b3);
        __threadfence();
        int done = atomicAdd(&g_done, 1);
        if (done == (int)gridDim.x - 1) {
            g_done = 0;                               // reset for next replay
            double inv = 1.0 / (double)N;
            double lp = ((volatile double*)g_acc)[0] * inv;
            double la = ((volatile double*)g_acc)[1] * inv;
            double lw = ((volatile double*)g_acc)[2] * inv;
            double ls = ((volatile double*)g_acc)[3] * inv;
            out[0] = (float)lp;
            out[1] = (float)la;
            out[2] = (float)lw;
            out[3] = (float)ls;
            out[4] = (float)(lp + la + lw + 0.5 * ls);
        }
    }
}

extern "C" void kernel_launch(void* const* d_in, const int* in_sizes, int n_in,
                              void* d_out, int out_size) {
    const float* pred   = (const float*)d_in[0];
    const float* gt     = (const float*)d_in[1];
    const int*   counts = (const int*)d_in[2];
    float* out = (float*)d_out;

    int N = in_sizes[2];
    if (N > MAXN) N = MAXN;              // scratch guard (contract: N == 262144)
    int NB = (N + TILE - 1) / TILE;      // 64 tiles

    k_scan_local<<<NB, SCAN_BLK>>>(counts, N);
    k_scan_bsum<<<1, MAX_NB>>>(NB);
    k_main<<<1024, 256>>>(pred, gt, counts, out, N);
}

// round 6
// speedup vs baseline: 1.4101x; 1.4101x over previous
#include <cuda_runtime.h>
#include <math.h>

// ---------------- scratch (no allocation allowed) ----------------
#define MAXN   262144
#define SCAN_BLK 1024          // threads per scan block
#define TILE   4096            // segments per scan tile (4 per thread)
#define TILE_SHIFT 12
#define MAX_NB 128
__device__ int    g_off[MAXN];     // exclusive prefix within scan tile
__device__ int    g_bsum[MAX_NB];  // exclusive tile offsets after k2
__device__ double g_acc[4];        // lp, la, lw, ls sums
__device__ int    g_done = 0;      // completion counter for folded finalize

// ---------------- kernel 1: tile-local exclusive scan (warp-scan) -------------
__global__ void __launch_bounds__(SCAN_BLK) k_scan_local(const int* __restrict__ counts, int N) {
    __shared__ int wsum[32];
    const unsigned FULL = 0xffffffffu;
    int tid = threadIdx.x, lane = tid & 31, w = tid >> 5;
    int base4 = blockIdx.x * TILE + tid * 4;

    int4 v = make_int4(0, 0, 0, 0);
    if (base4 + 3 < N) v = *(const int4*)(counts + base4);
    else {
        if (base4 + 0 < N) v.x = counts[base4 + 0];
        if (base4 + 1 < N) v.y = counts[base4 + 1];
        if (base4 + 2 < N) v.z = counts[base4 + 2];
        if (base4 + 3 < N) v.w = counts[base4 + 3];
    }
    int s = v.x + v.y + v.z + v.w;

    int si = s;
    #pragma unroll
    for (int o = 1; o < 32; o <<= 1) {
        int t = __shfl_up_sync(FULL, si, o);
        if (lane >= o) si += t;
    }
    if (lane == 31) wsum[w] = si;
    __syncthreads();
    if (w == 0) {
        int ws = wsum[lane];
        int wi = ws;
        #pragma unroll
        for (int o = 1; o < 32; o <<= 1) {
            int t = __shfl_up_sync(FULL, wi, o);
            if (lane >= o) wi += t;
        }
        wsum[lane] = wi - ws;                       // exclusive warp offset
        if (lane == 31) g_bsum[blockIdx.x] = wi;    // tile total
    }
    __syncthreads();

    int base = wsum[w] + (si - s);
    if (base4 + 3 < N) {
        int4 o4;
        o4.x = base;
        o4.y = base + v.x;
        o4.z = base + v.x + v.y;
        o4.w = base + v.x + v.y + v.z;
        *(int4*)(g_off + base4) = o4;
    } else {
        int b = base;
        if (base4 + 0 < N) { g_off[base4 + 0] = b; b += v.x; }
        if (base4 + 1 < N) { g_off[base4 + 1] = b; b += v.y; }
        if (base4 + 2 < N) { g_off[base4 + 2] = b; }
    }
}

// ---------------- kernel 2: scan tile sums -> exclusive; zero accumulators ----
__global__ void k_scan_bsum(int NB) {
    __shared__ int sh[MAX_NB];
    int tid = threadIdx.x;
    int v = (tid < NB) ? g_bsum[tid] : 0;
    sh[tid] = v;
    __syncthreads();
    #pragma unroll
    for (int o = 1; o < MAX_NB; o <<= 1) {
        int t = (tid >= o) ? sh[tid - o] : 0;
        __syncthreads();
        sh[tid] += t;
        __syncthreads();
    }
    if (tid < NB) g_bsum[tid] = sh[tid] - v;
    if (tid < 4)  g_acc[tid] = 0.0;
}

// ---------------- main segmented loss + folded finalize -----------------------
struct Seg {
    float2 p23, p45, g23, g45;
    unsigned db;
    int cnt;
};

__device__ __forceinline__ void seg_load(
    const float* __restrict__ pred, const float* __restrict__ gt,
    const int* __restrict__ counts, int s, int M, int lane, Seg& S)
{
    S.cnt = __ldg(counts + s);
    int off = g_off[s] + g_bsum[s >> TILE_SHIFT];

    const float* pr = pred + (size_t)s * 6;
    float2 p01 = *(const float2*)(pr);
    S.p23 = *(const float2*)(pr + 2);
    S.p45 = *(const float2*)(pr + 4);

    int r = off + ((lane < S.cnt) ? lane : 0);
    r = (r < M - 1) ? r : (M - 1);
    const float* gr = gt + (size_t)r * 6;
    float2 g01 = *(const float2*)(gr);
    S.g23 = *(const float2*)(gr + 2);
    S.g45 = *(const float2*)(gr + 4);

    float dx = p01.x - g01.x, dy = p01.y - g01.y;
    float d  = dx * dx + dy * dy;
    S.db = (lane < S.cnt) ? __float_as_uint(d) : 0x7f800000u;
}

__device__ __forceinline__ void seg_reduce(
    const Seg& S, int lane, float& a0, float& a1, float& a2, float& a3)
{
    const unsigned FULL = 0xffffffffu;
    unsigned mn   = __reduce_min_sync(FULL, S.db);     // min dist bits (nonneg fp)
    unsigned mask = __ballot_sync(FULL, S.db == mn);   // winners; lowest lane = ref tie-break
    int winner = __ffs(mask) - 1;
    if (S.cnt > 0 && lane == winner) {
        float dmin = __uint_as_float(mn);
        a0 += 1.0f - expf(dmin * (-1.0f / 0.045f));    // 2*sigma^2 = 0.045
        a1 += fabsf(S.p23.x - S.g23.x) + fabsf(S.p23.y - S.g23.y);
        float dd = S.p45.x - S.g45.x, ad = fabsf(dd);
        a2 += (ad < 1.0f) ? 0.5f * dd * dd : ad - 0.5f;
        float x = S.p45.y, t = S.g45.y;
        if (t > 0.0f)
            a3 += fmaxf(x, 0.0f) - x * t + log1pf(expf(-fabsf(x)));
    }
}

__global__ void __launch_bounds__(256) k_main(
    const float* __restrict__ pred,
    const float* __restrict__ gt,
    const int*   __restrict__ counts,
    float* __restrict__ out,
    int N, int M)
{
    const unsigned FULL = 0xffffffffu;
    const int lane   = threadIdx.x & 31;
    const int wInBlk = threadIdx.x >> 5;
    const int warpId = (blockIdx.x * blockDim.x + threadIdx.x) >> 5;
    const int nWarps = (gridDim.x * blockDim.x) >> 5;

    float a0 = 0.f, a1 = 0.f, a2 = 0.f, a3 = 0.f;

    int s = warpId;
    for (; s + nWarps < N; s += 2 * nWarps) {
        Seg A, B;
        seg_load(pred, gt, counts, s,          M, lane, A);   // 8 loads batched
        seg_load(pred, gt, counts, s + nWarps, M, lane, B);
        seg_reduce(A, lane, a0, a1, a2, a3);
        seg_reduce(B, lane, a0, a1, a2, a3);
    }
    if (s < N) {
        Seg A;
        seg_load(pred, gt, counts, s, M, lane, A);
        seg_reduce(A, lane, a0, a1, a2, a3);
    }

    // warp reduce (all lanes hold partials now)
    #pragma unroll
    for (int o = 16; o; o >>= 1) {
        a0 += __shfl_xor_sync(FULL, a0, o);
        a1 += __shfl_xor_sync(FULL, a1, o);
        a2 += __shfl_xor_sync(FULL, a2, o);
        a3 += __shfl_xor_sync(FULL, a3, o);
    }

    __shared__ float sh[8][4];
    if (lane == 0) {
        sh[wInBlk][0] = a0; sh[wInBlk][1] = a1;
        sh[wInBlk][2] = a2; sh[wInBlk][3] = a3;
    }
    __syncthreads();
    if (threadIdx.x == 0) {
        float b0 = 0.f, b1 = 0.f, b2 = 0.f, b3 = 0.f;
        int nw = blockDim.x >> 5;
        for (int w = 0; w < nw; w++) {
            b0 += sh[w][0]; b1 += sh[w][1]; b2 += sh[w][2]; b3 += sh[w][3];
        }
        atomicAdd(&g_acc[0], (double)b0);
        atomicAdd(&g_acc[1], (double)b1);
        atomicAdd(&g_acc[2], (double)b2);
        atomicAdd(&g_acc[3], (double)b3);
        __threadfence();
        int done = atomicAdd(&g_done, 1);
        if (done == (int)gridDim.x - 1) {
            g_done = 0;                               // reset for next replay
            double inv = 1.0 / (double)N;
            double lp = ((volatile double*)g_acc)[0] * inv;
            double la = ((volatile double*)g_acc)[1] * inv;
            double lw = ((volatile double*)g_acc)[2] * inv;
            double ls = ((volatile double*)g_acc)[3] * inv;
            out[0] = (float)lp;
            out[1] = (float)la;
            out[2] = (float)lw;
            out[3] = (float)ls;
            out[4] = (float)(lp + la + lw + 0.5 * ls);
        }
    }
}

extern "C" void kernel_launch(void* const* d_in, const int* in_sizes, int n_in,
                              void* d_out, int out_size) {
    const float* pred   = (const float*)d_in[0];
    const float* gt     = (const float*)d_in[1];
    const int*   counts = (const int*)d_in[2];
    float* out = (float*)d_out;

    int N = in_sizes[2];
    if (N > MAXN) N = MAXN;              // scratch guard (contract: N == 262144)
    int M = in_sizes[1] / 6;             // total gt rows
    int NB = (N + TILE - 1) / TILE;      // 64 tiles

    k_scan_local<<<NB, SCAN_BLK>>>(counts, N);
    k_scan_bsum<<<1, MAX_NB>>>(NB);
    k_main<<<2048, 256>>>(pred, gt, counts, out, N, M);
}